// round 1
// baseline (speedup 1.0000x reference)
#include <cuda_runtime.h>

// SSIM loss: pred/target (16,3,512,512) fp32, 11x11 gaussian (sigma=1.5)
// depthwise conv, zero padding, output = 1 - mean(ssim_map), single fp32 scalar.

#define HH 512
#define WW 512
#define PLANE (HH * WW)
#define NC 48                 // 16 batch * 3 channels
#define TILE_W 64
#define TILE_H 16
#define SH 26                 // TILE_H + 10
#define SWD 74                // TILE_W + 10
#define SPITCH 76             // padded shared row stride
#define GRID_X 8
#define GRID_Y 32
#define NBLOCKS (GRID_X * GRID_Y * NC)   // 12288
#define NPIX (16.0 * 3.0 * 512.0 * 512.0)

// gaussian(11, sigma=1.5), normalized (standard SSIM window values)
#define W0 0.001028380f
#define W1 0.007598758f
#define W2 0.036000773f
#define W3 0.109360702f
#define W4 0.213005530f
#define W5 0.266011730f

__device__ float g_partials[NBLOCKS];

__device__ __forceinline__ float wt(int k) {
    // k is always a compile-time constant after unrolling -> FFMA immediates
    switch (k) {
        case 0:  return W0;
        case 1:  return W1;
        case 2:  return W2;
        case 3:  return W3;
        case 4:  return W4;
        case 5:  return W5;
        case 6:  return W4;
        case 7:  return W3;
        case 8:  return W2;
        case 9:  return W1;
        default: return W0;
    }
}

__global__ void __launch_bounds__(256) ssim_main(
    const float* __restrict__ pred, const float* __restrict__ targ)
{
    __shared__ float sp[SH * SPITCH];
    __shared__ float st[SH * SPITCH];
    __shared__ float im[5][SH * TILE_W];
    __shared__ float wsum[8];

    const int tid = threadIdx.x;
    const int bx = blockIdx.x, by = blockIdx.y, z = blockIdx.z;

    const float* __restrict__ pbase = pred + (size_t)z * PLANE;
    const float* __restrict__ tbase = targ + (size_t)z * PLANE;
    const int gx0 = bx * TILE_W - 5;
    const int gy0 = by * TILE_H - 5;

    // ---- load halo tile (zero pad outside image) ----
    for (int i = tid; i < SH * SWD; i += 256) {
        int r = i / SWD;
        int c = i - r * SWD;
        int gr = gy0 + r;
        int gc = gx0 + c;
        float pv = 0.f, tv = 0.f;
        if ((unsigned)gr < (unsigned)HH && (unsigned)gc < (unsigned)WW) {
            size_t off = (size_t)gr * WW + gc;
            pv = pbase[off];
            tv = tbase[off];
        }
        sp[r * SPITCH + c] = pv;
        st[r * SPITCH + c] = tv;
    }
    __syncthreads();

    // ---- horizontal pass: 26 rows x 16 col-groups of 4 = 416 tasks ----
    // Each task streams 14 columns; each loaded value feeds up to 4 output
    // accumulators (shares LDS traffic 4-ways).
    for (int t = tid; t < SH * 16; t += 256) {
        int r  = t >> 4;
        int c0 = (t & 15) * 4;
        float ax[4]  = {0.f, 0.f, 0.f, 0.f};
        float ay[4]  = {0.f, 0.f, 0.f, 0.f};
        float axx[4] = {0.f, 0.f, 0.f, 0.f};
        float ayy[4] = {0.f, 0.f, 0.f, 0.f};
        float axy[4] = {0.f, 0.f, 0.f, 0.f};
        #pragma unroll
        for (int cc = 0; cc < 14; ++cc) {
            float p = sp[r * SPITCH + c0 + cc];
            float q = st[r * SPITCH + c0 + cc];
            float pp = p * p;
            float qq = q * q;
            float pq = p * q;
            #pragma unroll
            for (int o = 0; o < 4; ++o) {
                const int k = cc - o;
                if (k >= 0 && k < 11) {
                    ax[o]  = fmaf(wt(k), p,  ax[o]);
                    ay[o]  = fmaf(wt(k), q,  ay[o]);
                    axx[o] = fmaf(wt(k), pp, axx[o]);
                    ayy[o] = fmaf(wt(k), qq, ayy[o]);
                    axy[o] = fmaf(wt(k), pq, axy[o]);
                }
            }
        }
        #pragma unroll
        for (int o = 0; o < 4; ++o) {
            int idx = r * TILE_W + c0 + o;
            im[0][idx] = ax[o];
            im[1][idx] = ay[o];
            im[2][idx] = axx[o];
            im[3][idx] = ayy[o];
            im[4][idx] = axy[o];
        }
    }
    __syncthreads();

    // ---- vertical pass + ssim: 64 cols x 4 row-groups of 4 = 256 tasks ----
    float lsum = 0.f;
    {
        const int c  = tid & 63;
        const int r0 = (tid >> 6) * 4;
        float ax[4]  = {0.f, 0.f, 0.f, 0.f};
        float ay[4]  = {0.f, 0.f, 0.f, 0.f};
        float axx[4] = {0.f, 0.f, 0.f, 0.f};
        float ayy[4] = {0.f, 0.f, 0.f, 0.f};
        float axy[4] = {0.f, 0.f, 0.f, 0.f};
        #pragma unroll
        for (int rr = 0; rr < 14; ++rr) {
            int row = r0 + rr;
            float m0 = im[0][row * TILE_W + c];
            float m1 = im[1][row * TILE_W + c];
            float m2 = im[2][row * TILE_W + c];
            float m3 = im[3][row * TILE_W + c];
            float m4 = im[4][row * TILE_W + c];
            #pragma unroll
            for (int o = 0; o < 4; ++o) {
                const int k = rr - o;
                if (k >= 0 && k < 11) {
                    ax[o]  = fmaf(wt(k), m0, ax[o]);
                    ay[o]  = fmaf(wt(k), m1, ay[o]);
                    axx[o] = fmaf(wt(k), m2, axx[o]);
                    ayy[o] = fmaf(wt(k), m3, ayy[o]);
                    axy[o] = fmaf(wt(k), m4, axy[o]);
                }
            }
        }
        const float C1 = 1e-4f;   // 0.01^2
        const float C2 = 9e-4f;   // 0.03^2
        #pragma unroll
        for (int o = 0; o < 4; ++o) {
            float mx  = ax[o],  my  = ay[o];
            float mxx = mx * mx;
            float myy = my * my;
            float mxy = mx * my;
            float vx  = axx[o] - mxx;
            float vy  = ayy[o] - myy;
            float vxy = axy[o] - mxy;
            float num = fmaf(2.f, mxy, C1) * fmaf(2.f, vxy, C2);
            float den = (mxx + myy + C1) * (vx + vy + C2);
            lsum += __fdividef(num, den);
        }
    }

    // ---- block reduction ----
    #pragma unroll
    for (int s = 16; s > 0; s >>= 1)
        lsum += __shfl_xor_sync(0xffffffffu, lsum, s);
    if ((tid & 31) == 0) wsum[tid >> 5] = lsum;
    __syncthreads();
    if (tid == 0) {
        float bs = 0.f;
        #pragma unroll
        for (int i = 0; i < 8; ++i) bs += wsum[i];
        g_partials[blockIdx.x + GRID_X * (blockIdx.y + GRID_Y * blockIdx.z)] = bs;
    }
}

__global__ void __launch_bounds__(256) ssim_finalize(float* __restrict__ out)
{
    __shared__ double ws[8];
    double s = 0.0;
    for (int i = threadIdx.x; i < NBLOCKS; i += 256)
        s += (double)g_partials[i];
    #pragma unroll
    for (int sh = 16; sh > 0; sh >>= 1)
        s += __shfl_xor_sync(0xffffffffu, s, sh);
    if ((threadIdx.x & 31) == 0) ws[threadIdx.x >> 5] = s;
    __syncthreads();
    if (threadIdx.x == 0) {
        double tot = 0.0;
        #pragma unroll
        for (int i = 0; i < 8; ++i) tot += ws[i];
        out[0] = (float)(1.0 - tot / NPIX);
    }
}

extern "C" void kernel_launch(void* const* d_in, const int* in_sizes, int n_in,
                              void* d_out, int out_size)
{
    (void)in_sizes; (void)n_in; (void)out_size;
    const float* pred = (const float*)d_in[0];
    const float* targ = (const float*)d_in[1];
    dim3 grid(GRID_X, GRID_Y, NC);
    ssim_main<<<grid, 256>>>(pred, targ);
    ssim_finalize<<<1, 256>>>((float*)d_out);
}

// round 2
// speedup vs baseline: 1.3947x; 1.3947x over previous
#include <cuda_runtime.h>
#include <cstdint>

// SSIM loss: pred/target (16,3,512,512) fp32, 11x11 gaussian (sigma=1.5)
// depthwise conv, zero padding, out = 1 - mean(ssim_map).
// Separable conv, vertical pass first (packed f32x2 over column pairs),
// then horizontal pass (packed f32x2 over output-column pairs).

#define HH 512
#define WW 512
#define PLANE (HH * WW)
#define NC 48
#define TILE_W 64
#define TILE_H 32
#define SH 42                  // TILE_H + 10
#define SWD 74                 // TILE_W + 10
#define SPITCH 76              // input tile pitch (even, LDS.64-aligned)
#define IMPITCH 75             // intermediate pitch (odd -> conflict-free h-pass)
#define IM_PLANE (TILE_H * IMPITCH)
#define GRID_X 8               // 512/64
#define GRID_Y 16              // 512/32
#define NPIX (16.0 * 3.0 * 512.0 * 512.0)

#define SP_OFF 0
#define ST_OFF (SH * SPITCH)
#define IM_OFF (2 * SH * SPITCH)
#define SMEM_FLOATS (IM_OFF + 5 * IM_PLANE)   // 6384 + 12000 = 18384
#define SMEM_BYTES (SMEM_FLOATS * 4)          // 73536

// gaussian(11, sigma=1.5), normalized
#define W0 0.001028380f
#define W1 0.007598758f
#define W2 0.036000773f
#define W3 0.109360702f
#define W4 0.213005530f
#define W5 0.266011730f

__device__ float g_accum;   // zero-initialized at module load; reset by ssim_write

__device__ __forceinline__ float wt(int k) {
    switch (k) {
        case 0:  return W0;
        case 1:  return W1;
        case 2:  return W2;
        case 3:  return W3;
        case 4:  return W4;
        case 5:  return W5;
        case 6:  return W4;
        case 7:  return W3;
        case 8:  return W2;
        case 9:  return W1;
        default: return W0;
    }
}

// ---- packed f32x2 helpers (sm_103a) ----
__device__ __forceinline__ uint64_t pk2(float lo, float hi) {
    uint64_t r;
    asm("mov.b64 %0, {%1, %2};" : "=l"(r) : "f"(lo), "f"(hi));
    return r;
}
__device__ __forceinline__ void upk2(float& lo, float& hi, uint64_t v) {
    asm("mov.b64 {%0, %1}, %2;" : "=f"(lo), "=f"(hi) : "l"(v));
}
__device__ __forceinline__ uint64_t mul2(uint64_t a, uint64_t b) {
    uint64_t d;
    asm("mul.rn.f32x2 %0, %1, %2;" : "=l"(d) : "l"(a), "l"(b));
    return d;
}
__device__ __forceinline__ void fma2(uint64_t& d, uint64_t a, uint64_t b) {
    asm("fma.rn.f32x2 %0, %1, %2, %0;" : "+l"(d) : "l"(a), "l"(b));
}
__device__ __forceinline__ uint64_t wpair(int k) {
    float w = wt(k);
    return pk2(w, w);   // ptxas CSEs the 6 unique values
}

__global__ void __launch_bounds__(256, 2) ssim_main(
    const float* __restrict__ pred, const float* __restrict__ targ)
{
    extern __shared__ float smem[];
    float* sp = smem + SP_OFF;
    float* st = smem + ST_OFF;
    float* im = smem + IM_OFF;   // 5 planes of IM_PLANE floats
    __shared__ float wsum[8];

    const int tid = threadIdx.x;
    const int z = blockIdx.z;
    const float* __restrict__ pbase = pred + (size_t)z * PLANE;
    const float* __restrict__ tbase = targ + (size_t)z * PLANE;
    const int gx0 = blockIdx.x * TILE_W - 5;
    const int gy0 = blockIdx.y * TILE_H - 5;

    // ---- load halo tile (zero pad) ----
    for (int i = tid; i < SH * SWD; i += 256) {
        int r = i / SWD;
        int c = i - r * SWD;
        int gr = gy0 + r;
        int gc = gx0 + c;
        float pv = 0.f, tv = 0.f;
        if ((unsigned)gr < (unsigned)HH && (unsigned)gc < (unsigned)WW) {
            size_t off = (size_t)gr * WW + gc;
            pv = pbase[off];
            tv = tbase[off];
        }
        sp[r * SPITCH + c] = pv;
        st[r * SPITCH + c] = tv;
    }
    __syncthreads();

    // ---- vertical pass (packed over column pairs) ----
    // 37 column pairs x 8 row groups (4 rows each) = 296 tasks
    for (int t = tid; t < 37 * 8; t += 256) {
        const int cp = t % 37;
        const int rg = t / 37;
        const int r0 = rg * 4;
        const int cb = 2 * cp;          // even -> 8B aligned

        uint64_t ax[4], ay[4], axx[4], ayy[4], axy[4];
        #pragma unroll
        for (int o = 0; o < 4; ++o) { ax[o]=0; ay[o]=0; axx[o]=0; ayy[o]=0; axy[o]=0; }

        #pragma unroll
        for (int rr = 0; rr < 14; ++rr) {
            uint64_t P = *(const uint64_t*)&sp[(r0 + rr) * SPITCH + cb];
            uint64_t Q = *(const uint64_t*)&st[(r0 + rr) * SPITCH + cb];
            uint64_t PP = mul2(P, P);
            uint64_t QQ = mul2(Q, Q);
            uint64_t PQ = mul2(P, Q);
            #pragma unroll
            for (int o = 0; o < 4; ++o) {
                const int k = rr - o;
                if (k >= 0 && k < 11) {
                    const uint64_t w = wpair(k);
                    fma2(ax[o],  w, P);
                    fma2(ay[o],  w, Q);
                    fma2(axx[o], w, PP);
                    fma2(ayy[o], w, QQ);
                    fma2(axy[o], w, PQ);
                }
            }
        }
        #pragma unroll
        for (int o = 0; o < 4; ++o) {
            const int base = (r0 + o) * IMPITCH + cb;
            float lo, hi;
            upk2(lo, hi, ax[o]);  im[0*IM_PLANE + base] = lo; im[0*IM_PLANE + base + 1] = hi;
            upk2(lo, hi, ay[o]);  im[1*IM_PLANE + base] = lo; im[1*IM_PLANE + base + 1] = hi;
            upk2(lo, hi, axx[o]); im[2*IM_PLANE + base] = lo; im[2*IM_PLANE + base + 1] = hi;
            upk2(lo, hi, ayy[o]); im[3*IM_PLANE + base] = lo; im[3*IM_PLANE + base + 1] = hi;
            upk2(lo, hi, axy[o]); im[4*IM_PLANE + base] = lo; im[4*IM_PLANE + base + 1] = hi;
        }
    }
    __syncthreads();

    // ---- horizontal pass + SSIM ----
    // lane = output row (0..31), warp = column group of 8 (4 output pairs)
    float lsum = 0.f;
    {
        const int r  = tid & 31;
        const int c0 = (tid >> 5) * 8;
        const int rbase = r * IMPITCH + c0;

        uint64_t acc[5][4];
        #pragma unroll
        for (int m = 0; m < 5; ++m)
            #pragma unroll
            for (int j = 0; j < 4; ++j) acc[m][j] = 0;

        float prev[5];
        #pragma unroll
        for (int cc = 0; cc < 18; ++cc) {
            float cur[5];
            #pragma unroll
            for (int m = 0; m < 5; ++m)
                cur[m] = im[m * IM_PLANE + rbase + cc];
            if (cc > 0) {
                const int s = cc - 1;                 // pair start offset
                uint64_t pr[5];
                #pragma unroll
                for (int m = 0; m < 5; ++m) pr[m] = pk2(prev[m], cur[m]);
                #pragma unroll
                for (int j = 0; j < 4; ++j) {
                    const int k = s - 2 * j;
                    if (k >= 0 && k < 11) {
                        const uint64_t w = wpair(k);
                        #pragma unroll
                        for (int m = 0; m < 5; ++m) fma2(acc[m][j], w, pr[m]);
                    }
                }
            }
            #pragma unroll
            for (int m = 0; m < 5; ++m) prev[m] = cur[m];
        }

        const float C1 = 1e-4f;
        const float C2 = 9e-4f;
        #pragma unroll
        for (int j = 0; j < 4; ++j) {
            float mx[2], my[2], exx[2], eyy[2], exy[2];
            upk2(mx[0],  mx[1],  acc[0][j]);
            upk2(my[0],  my[1],  acc[1][j]);
            upk2(exx[0], exx[1], acc[2][j]);
            upk2(eyy[0], eyy[1], acc[3][j]);
            upk2(exy[0], exy[1], acc[4][j]);
            #pragma unroll
            for (int h = 0; h < 2; ++h) {
                float mxx = mx[h] * mx[h];
                float myy = my[h] * my[h];
                float mxy = mx[h] * my[h];
                float vx  = exx[h] - mxx;
                float vy  = eyy[h] - myy;
                float vxy = exy[h] - mxy;
                float num = fmaf(2.f, mxy, C1) * fmaf(2.f, vxy, C2);
                float den = (mxx + myy + C1) * (vx + vy + C2);
                lsum += __fdividef(num, den);
            }
        }
    }

    // ---- block reduction + global atomic ----
    #pragma unroll
    for (int s = 16; s > 0; s >>= 1)
        lsum += __shfl_xor_sync(0xffffffffu, lsum, s);
    if ((tid & 31) == 0) wsum[tid >> 5] = lsum;
    __syncthreads();
    if (tid == 0) {
        float bs = 0.f;
        #pragma unroll
        for (int i = 0; i < 8; ++i) bs += wsum[i];
        atomicAdd(&g_accum, bs);
    }
}

__global__ void ssim_write(float* __restrict__ out)
{
    float s = g_accum;
    out[0] = (float)(1.0 - (double)s / NPIX);
    g_accum = 0.f;          // reset for next graph replay
}

extern "C" void kernel_launch(void* const* d_in, const int* in_sizes, int n_in,
                              void* d_out, int out_size)
{
    (void)in_sizes; (void)n_in; (void)out_size;
    const float* pred = (const float*)d_in[0];
    const float* targ = (const float*)d_in[1];

    cudaFuncSetAttribute(ssim_main,
                         cudaFuncAttributeMaxDynamicSharedMemorySize, SMEM_BYTES);

    dim3 grid(GRID_X, GRID_Y, NC);
    ssim_main<<<grid, 256, SMEM_BYTES>>>(pred, targ);
    ssim_write<<<1, 1>>>((float*)d_out);
}